// round 3
// baseline (speedup 1.0000x reference)
#include <cuda_runtime.h>
#include <cuda_bf16.h>
#include <cstdint>

// Problem constants
#define T_ 64
#define B_ 16
#define DIM_ 512
#define H_ 8
#define DH_ 64
#define ETA_ 4
#define FD_ 256           // ETA_*DH_
#define NPROJ 2656        // 5*512 + 3*32
#define NPROJ_PAD 2688    // 42 * 64
#define MROWS 1024        // T_*B_

// Output layout (tuple flattened): output[T,B,DIM], kv_last[B,H,FD,Dh], nm_last[B,H,FD]
#define OUT_OFF_KV  (T_*B_*DIM_)                 // 524288
#define OUT_OFF_NM  (OUT_OFF_KV + B_*H_*FD_*DH_) // 524288 + 2097152

// Scratch (device globals — no allocation allowed)
__device__ float g_proj[MROWS * NPROJ_PAD];   // ~11 MB, projections row-major
__device__ float g_attn[MROWS * (H_*DH_)];    // 2 MB, attn_out before Wo

// ---------------------------------------------------------------------------
// GEMM 1: projections.  C[m, n] = sum_k X[m,k] * W(n)[k]
// X: [1024, 512] row-major.  Column n maps to one of 8 weight matrices.
// Tile: BM=64, BN=64, BK=16, 256 threads, 4x4 microtile.
// ---------------------------------------------------------------------------
#define BM 64
#define BN 64
#define BK 16

__global__ __launch_bounds__(256)
void proj_gemm(const float* __restrict__ X,
               const float* __restrict__ Wq, const float* __restrict__ Wk,
               const float* __restrict__ Wv, const float* __restrict__ Wb,
               const float* __restrict__ Wg, const float* __restrict__ Wp1,
               const float* __restrict__ Wp2, const float* __restrict__ Wp3)
{
    __shared__ float Xs[BK][BM + 4];
    __shared__ float Ws[BK][BN + 4];

    const int tid = threadIdx.x;
    const int m0 = blockIdx.y * BM;
    const int n0 = blockIdx.x * BN;

    // load roles: thread loads one float4 of a row (64 rows x 16 k each tile)
    const int lr = tid >> 2;          // 0..63 : row within tile
    const int lc = (tid & 3) * 4;     // 0,4,8,12 : k offset

    // compute roles
    const int tx = tid & 15;          // n micro
    const int ty = tid >> 4;          // m micro

    // Resolve the weight row pointer for global column (n0 + lr)
    const int n = n0 + lr;
    const float* wrow = nullptr;
    if (n < 2560) {
        const int wi = n >> 9;
        const int nl = n & 511;
        const float* wb = (wi == 0) ? Wq : (wi == 1) ? Wk : (wi == 2) ? Wv
                         : (wi == 3) ? Wb : Wg;
        wrow = wb + nl * DIM_;
    } else if (n < NPROJ) {
        const int nn = n - 2560;
        const int wi = nn >> 5;
        const int nl = nn & 31;
        const float* wb = (wi == 0) ? Wp1 : (wi == 1) ? Wp2 : Wp3;
        wrow = wb + nl * DIM_;
    }
    const float* xrow = X + (size_t)(m0 + lr) * DIM_;

    float acc[4][4];
#pragma unroll
    for (int i = 0; i < 4; i++)
#pragma unroll
        for (int j = 0; j < 4; j++) acc[i][j] = 0.f;

    for (int k0 = 0; k0 < DIM_; k0 += BK) {
        float4 xv = *(const float4*)(xrow + k0 + lc);
        float4 wv = make_float4(0.f, 0.f, 0.f, 0.f);
        if (wrow) wv = *(const float4*)(wrow + k0 + lc);
        Xs[lc + 0][lr] = xv.x; Xs[lc + 1][lr] = xv.y;
        Xs[lc + 2][lr] = xv.z; Xs[lc + 3][lr] = xv.w;
        Ws[lc + 0][lr] = wv.x; Ws[lc + 1][lr] = wv.y;
        Ws[lc + 2][lr] = wv.z; Ws[lc + 3][lr] = wv.w;
        __syncthreads();
#pragma unroll
        for (int kk = 0; kk < BK; kk++) {
            float4 a = *(const float4*)&Xs[kk][ty * 4];
            float4 bq = *(const float4*)&Ws[kk][tx * 4];
            float av[4] = {a.x, a.y, a.z, a.w};
            float bv[4] = {bq.x, bq.y, bq.z, bq.w};
#pragma unroll
            for (int i = 0; i < 4; i++)
#pragma unroll
                for (int j = 0; j < 4; j++) acc[i][j] += av[i] * bv[j];
        }
        __syncthreads();
    }

#pragma unroll
    for (int i = 0; i < 4; i++) {
        const int m = m0 + ty * 4 + i;
#pragma unroll
        for (int j = 0; j < 4; j++) {
            g_proj[(size_t)m * NPROJ_PAD + n0 + tx * 4 + j] = acc[i][j];
        }
    }
}

// ---------------------------------------------------------------------------
// GEMM 2: output.  out[m, n] = sum_k attn[m,k] * Wo[n,k] + bo[n]
// ---------------------------------------------------------------------------
__global__ __launch_bounds__(256)
void out_gemm(const float* __restrict__ Wo, const float* __restrict__ bo,
              float* __restrict__ out)
{
    __shared__ float Xs[BK][BM + 4];
    __shared__ float Ws[BK][BN + 4];

    const int tid = threadIdx.x;
    const int m0 = blockIdx.y * BM;
    const int n0 = blockIdx.x * BN;
    const int lr = tid >> 2;
    const int lc = (tid & 3) * 4;
    const int tx = tid & 15;
    const int ty = tid >> 4;

    const float* xrow = g_attn + (size_t)(m0 + lr) * DIM_;
    const float* wrow = Wo + (size_t)(n0 + lr) * DIM_;

    float acc[4][4];
#pragma unroll
    for (int i = 0; i < 4; i++)
#pragma unroll
        for (int j = 0; j < 4; j++) acc[i][j] = 0.f;

    for (int k0 = 0; k0 < DIM_; k0 += BK) {
        float4 xv = *(const float4*)(xrow + k0 + lc);
        float4 wv = *(const float4*)(wrow + k0 + lc);
        Xs[lc + 0][lr] = xv.x; Xs[lc + 1][lr] = xv.y;
        Xs[lc + 2][lr] = xv.z; Xs[lc + 3][lr] = xv.w;
        Ws[lc + 0][lr] = wv.x; Ws[lc + 1][lr] = wv.y;
        Ws[lc + 2][lr] = wv.z; Ws[lc + 3][lr] = wv.w;
        __syncthreads();
#pragma unroll
        for (int kk = 0; kk < BK; kk++) {
            float4 a = *(const float4*)&Xs[kk][ty * 4];
            float4 bq = *(const float4*)&Ws[kk][tx * 4];
            float av[4] = {a.x, a.y, a.z, a.w};
            float bv[4] = {bq.x, bq.y, bq.z, bq.w};
#pragma unroll
            for (int i = 0; i < 4; i++)
#pragma unroll
                for (int j = 0; j < 4; j++) acc[i][j] += av[i] * bv[j];
        }
        __syncthreads();
    }

#pragma unroll
    for (int i = 0; i < 4; i++) {
        const int m = m0 + ty * 4 + i;
#pragma unroll
        for (int j = 0; j < 4; j++) {
            const int nn = n0 + tx * 4 + j;
            out[(size_t)m * DIM_ + nn] = acc[i][j] + bo[nn];
        }
    }
}

// ---------------------------------------------------------------------------
// Scan kernel: one block per (b, h).  256 threads.
//
// Thread roles:
//  role A ("ED" role): tid = ED in [0,256): computes per-feature quantities
//     disc/gk/phi, carries nm[ED], contributes to den.
//  role B ("(eg,d)" role): eg = tid>>6, d = tid&63: owns kv[eg*64+j][d],
//     j = 0..63 in registers; num[d] needs only a 4-way reduction over eg.
// ---------------------------------------------------------------------------
__device__ __forceinline__ float sigmoidf_(float x) {
    return 1.f / (1.f + __expf(-x));
}

__global__ __launch_bounds__(256)
void scan_kernel(const int* __restrict__ term,
                 const float* __restrict__ kv_prev,
                 const float* __restrict__ nm_prev,
                 float* __restrict__ kv_out,
                 float* __restrict__ nm_out)
{
    const int bh = blockIdx.x;       // 0..127
    const int b  = bh >> 3;
    const int h  = bh & 7;
    const int tid = threadIdx.x;
    const int eg = tid >> 6;         // 0..3
    const int d  = tid & 63;
    const int ED = tid;
    const int e  = ED >> 6;
    const int dd = ED & 63;

    __shared__ float s_disc[FD_];
    __shared__ float s_gk[FD_];
    __shared__ float s_phi[FD_];
    __shared__ float s_gv[DH_];
    __shared__ float s_numred[4][DH_];
    __shared__ float s_denred[8];
    __shared__ float s_den;

    // Load kv state into registers
    float kv[64];
    const float* kvp = kv_prev + (size_t)bh * FD_ * DH_;
#pragma unroll
    for (int j = 0; j < 64; j++) kv[j] = kvp[(eg * 64 + j) * DH_ + d];
    float nm = nm_prev[bh * FD_ + ED];

    const int hcol = h * DH_;

    for (int t = 0; t < T_; t++) {
        const int row = t * B_ + b;
        const float* P = g_proj + (size_t)row * NPROJ_PAD;

        // ---- phase A: per-ED quantities ----
        const float kdd    = P[512 + hcol + dd];
        const float sgamma = sigmoidf_(P[2048 + hcol + dd]);
        const float p1e = P[2560 + h * ETA_ + e];
        const float p2e = P[2592 + h * ETA_ + e];
        const float p3e = P[2624 + h * ETA_ + e];
        const float gf  = sigmoidf_(p3e) * sgamma;
        const float mask = term[t * B_ + b] ? 0.f : 1.f;
        const float disc = (1.f - gf) * mask;
        const float gkv  = fmaxf(p1e, 0.f) * kdd * gf;
        const float qdd  = P[hcol + dd];
        const float phi  = fmaxf(p2e, 0.f) * qdd;

        s_disc[ED] = disc;
        s_gk[ED]   = gkv;
        s_phi[ED]  = phi;

        nm = disc * nm + gkv;
        float denp = phi * nm;
#pragma unroll
        for (int o = 16; o; o >>= 1)
            denp += __shfl_xor_sync(0xFFFFFFFFu, denp, o);
        if ((tid & 31) == 0) s_denred[tid >> 5] = denp;

        if (tid < 64) {
            const float vv = P[1024 + hcol + tid];
            const float bb = P[1536 + hcol + tid];
            s_gv[tid] = vv * sigmoidf_(bb);
        }
        __syncthreads();

        // thread 0 finalizes den while everyone starts phase B
        if (tid == 0) {
            float den = 0.f;
#pragma unroll
            for (int w = 0; w < 8; w++) den += s_denred[w];
            s_den = den;
        }

        // ---- phase B: kv recurrence + num contraction ----
        const float gvd = s_gv[d];
        const float* dsc = &s_disc[eg * 64];
        const float* gks = &s_gk[eg * 64];
        const float* phs = &s_phi[eg * 64];
        float np = 0.f;
#pragma unroll
        for (int jq = 0; jq < 16; jq++) {
            float4 D  = ((const float4*)dsc)[jq];
            float4 G  = ((const float4*)gks)[jq];
            float4 Ph = ((const float4*)phs)[jq];
            float k0v = fmaf(D.x, kv[4*jq+0], gvd * G.x);
            float k1v = fmaf(D.y, kv[4*jq+1], gvd * G.y);
            float k2v = fmaf(D.z, kv[4*jq+2], gvd * G.z);
            float k3v = fmaf(D.w, kv[4*jq+3], gvd * G.w);
            kv[4*jq+0] = k0v; kv[4*jq+1] = k1v;
            kv[4*jq+2] = k2v; kv[4*jq+3] = k3v;
            np = fmaf(k0v, Ph.x, np);
            np = fmaf(k1v, Ph.y, np);
            np = fmaf(k2v, Ph.z, np);
            np = fmaf(k3v, Ph.w, np);
        }
        s_numred[eg][d] = np;
        __syncthreads();

        // ---- phase C: finalize attn_out ----
        if (tid < 64) {
            const float num = s_numred[0][tid] + s_numred[1][tid]
                            + s_numred[2][tid] + s_numred[3][tid];
            g_attn[(size_t)row * (H_*DH_) + hcol + tid] = num / (s_den + 1e-6f);
        }
        // no extra sync needed: next phase-A writes disjoint arrays; phase-B
        // writes to s_numred are separated from phase-C reads by next sync.
    }

    // Write final states
    float* kvo = kv_out + (size_t)bh * FD_ * DH_;
#pragma unroll
    for (int j = 0; j < 64; j++) kvo[(eg * 64 + j) * DH_ + d] = kv[j];
    nm_out[bh * FD_ + ED] = nm;
}

// ---------------------------------------------------------------------------
// Launch
// ---------------------------------------------------------------------------
extern "C" void kernel_launch(void* const* d_in, const int* in_sizes, int n_in,
                              void* d_out, int out_size)
{
    const float* X    = (const float*)d_in[0];
    const int*   term = (const int*)d_in[1];
    const float* kvp  = (const float*)d_in[2];
    const float* nmp  = (const float*)d_in[3];
    const float* Wq   = (const float*)d_in[4];
    const float* Wk   = (const float*)d_in[5];
    const float* Wv   = (const float*)d_in[6];
    const float* Wb   = (const float*)d_in[7];
    const float* Wg   = (const float*)d_in[8];
    const float* Wp1  = (const float*)d_in[9];
    const float* Wp2  = (const float*)d_in[10];
    const float* Wp3  = (const float*)d_in[11];
    const float* Wo   = (const float*)d_in[12];
    const float* bo   = (const float*)d_in[13];
    float* out = (float*)d_out;

    dim3 gp(NPROJ_PAD / BN, MROWS / BM);   // 42 x 16
    proj_gemm<<<gp, 256>>>(X, Wq, Wk, Wv, Wb, Wg, Wp1, Wp2, Wp3);

    scan_kernel<<<B_ * H_, 256>>>(term, kvp, nmp,
                                  out + OUT_OFF_KV, out + OUT_OFF_NM);

    dim3 go(DIM_ / BN, MROWS / BM);        // 8 x 16
    out_gemm<<<go, 256>>>(Wo, bo, out);
}